// round 2
// baseline (speedup 1.0000x reference)
#include <cuda_runtime.h>

// FastAttention (Performer / FAVOR+) — fp32 SIMT baseline.
// B=4 H=8 N=4096 D=64 M=266 E=64.
// Round 1 fix: q'/k' row stride padded 266 -> 272 so all float4 LDG/STG are
// 16B-aligned (266%4==2 made odd rows misaligned -> "misaligned address").

#define BHc 32
#define NN  4096
#define DD  64
#define MM  266
#define MSTR 272          // padded row stride for q'/k' (multiple of 4 floats)
#define EE  64

#define DN     0.3535533905932738f     // 64^-0.25
#define RATIO  0.06131393394849658f    // 266^-0.5
#define EPSV   1e-4f
#define NEGINF (-3.402823466e38f)

#define KCHUNKS 16
#define SPLITK  4

// ---- scratch (static device arrays: no runtime allocation) ----
__device__ float    g_qp[BHc * NN * MSTR];               // q' [bh][n][m]
__device__ float    g_kd[BHc * NN * MSTR];               // kd-diag, then k' in place
__device__ unsigned g_kmax_bits;                         // ordered-uint encoded global max
__device__ float    g_kcum_part[KCHUNKS * BHc * MM];
__device__ float    g_kcum[BHc * MM];
__device__ float    g_ctx_part[SPLITK * BHc * MM * EE];
__device__ float    g_ctx[BHc * MM * EE];

__global__ void k_reset() { if (threadIdx.x == 0) g_kmax_bits = 0u; }

// ---------------------------------------------------------------------------
// Projection kernel: one block = 64 rows x full M. Computes data_dash into
// shared, then (Q) rowmax+diag+exp fused, or (K) diag subtract + block max.
// ---------------------------------------------------------------------------
template <bool IS_Q>
__global__ void __launch_bounds__(256) k_proj(const float* __restrict__ X,
                                              const float* __restrict__ P)
{
    extern __shared__ float sh[];
    float* sX    = sh;                 // [64][65]  scaled rows (row-major [r][k])
    float* sP    = sh + 64 * 65;       // [64][65]  projection tile ([m][k])
    float* sD    = sh + 2 * 64 * 65;   // [64][272] data_dash stash
    float* sMax  = sD + 64 * 272;      // [64]
    float* sDiag = sMax + 64;          // [64]
    float* sRed  = sDiag + 64;         // [8]

    const int tid = threadIdx.x;
    const int tx = tid & 15, ty = tid >> 4;
    const int bh = blockIdx.y;
    const int r0 = blockIdx.x * 64;
    const float* Xb = X + ((size_t)bh * NN + r0) * DD;
    float* OUT = (IS_Q ? g_qp : g_kd) + ((size_t)bh * NN + r0) * MSTR;

    // load X rows, pre-scaled by data_normalizer
    {
        const int k4 = (tid & 15) * 4;
        const int rr = tid >> 4;
        #pragma unroll
        for (int j = 0; j < 4; j++) {
            int r = rr + 16 * j;
            float4 v = *(const float4*)(Xb + (size_t)r * DD + k4);
            sX[r * 65 + k4 + 0] = v.x * DN;
            sX[r * 65 + k4 + 1] = v.y * DN;
            sX[r * 65 + k4 + 2] = v.z * DN;
            sX[r * 65 + k4 + 3] = v.w * DN;
        }
    }

    #pragma unroll 1
    for (int t = 0; t < 5; t++) {
        const int m0 = t * 64;
        __syncthreads();
        // load P tile rows m0..m0+63 ([m][k]); zero-pad m >= 266
        {
            const int k4 = (tid & 15) * 4;
            const int rr = tid >> 4;
            #pragma unroll
            for (int j = 0; j < 4; j++) {
                int ml = rr + 16 * j;
                int m = m0 + ml;
                float x0 = 0.f, x1 = 0.f, x2 = 0.f, x3 = 0.f;
                if (m < MM) {
                    float4 v = *(const float4*)(P + (size_t)m * DD + k4);
                    x0 = v.x; x1 = v.y; x2 = v.z; x3 = v.w;
                }
                sP[ml * 65 + k4 + 0] = x0; sP[ml * 65 + k4 + 1] = x1;
                sP[ml * 65 + k4 + 2] = x2; sP[ml * 65 + k4 + 3] = x3;
            }
        }
        __syncthreads();

        float acc[4][4];
        #pragma unroll
        for (int i = 0; i < 4; i++)
            #pragma unroll
            for (int j = 0; j < 4; j++) acc[i][j] = 0.f;

        #pragma unroll 8
        for (int kk = 0; kk < 64; kk++) {
            float a[4], b[4];
            #pragma unroll
            for (int i = 0; i < 4; i++) a[i] = sX[(4 * ty + i) * 65 + kk];
            #pragma unroll
            for (int j = 0; j < 4; j++) b[j] = sP[(4 * tx + j) * 65 + kk];
            #pragma unroll
            for (int i = 0; i < 4; i++)
                #pragma unroll
                for (int j = 0; j < 4; j++)
                    acc[i][j] = fmaf(a[i], b[j], acc[i][j]);
        }

        #pragma unroll
        for (int i = 0; i < 4; i++) {
            int row = 4 * ty + i;
            #pragma unroll
            for (int j = 0; j < 4; j++) {
                int m = m0 + 4 * tx + j;
                if (m < MM) sD[row * 272 + m] = acc[i][j];
            }
        }
    }
    __syncthreads();

    // per-row diag (and rowmax for Q): one warp handles 8 rows
    const int w = tid >> 5, lane = tid & 31;
    for (int s = 0; s < 8; s++) {
        int r = w * 8 + s;
        float dg = 0.f;
        #pragma unroll
        for (int kk = lane; kk < 64; kk += 32) {
            float x = sX[r * 65 + kk];
            dg = fmaf(x, x, dg);
        }
        #pragma unroll
        for (int o = 16; o; o >>= 1) dg += __shfl_xor_sync(0xffffffffu, dg, o);
        float mx = NEGINF;
        if (IS_Q) {
            for (int m = lane; m < MM; m += 32) mx = fmaxf(mx, sD[r * 272 + m]);
            #pragma unroll
            for (int o = 16; o; o >>= 1) mx = fmaxf(mx, __shfl_xor_sync(0xffffffffu, mx, o));
        }
        if (lane == 0) {
            sDiag[r] = 0.5f * dg;   // since sX is pre-scaled, diag = 0.5 * sum(x_hat^2)
            if (IS_Q) sMax[r] = mx;
        }
    }
    __syncthreads();

    if (IS_Q) {
        for (int idx = tid; idx < 64 * MM; idx += 256) {
            int r = idx / MM, m = idx - r * MM;
            float val = RATIO * (__expf(sD[r * 272 + m] - sDiag[r] - sMax[r]) + EPSV);
            OUT[(size_t)r * MSTR + m] = val;
        }
    } else {
        float bm = NEGINF;
        for (int idx = tid; idx < 64 * MM; idx += 256) {
            int r = idx / MM, m = idx - r * MM;
            float d = sD[r * 272 + m];
            bm = fmaxf(bm, d);                        // stab uses raw data_dash
            OUT[(size_t)r * MSTR + m] = d - sDiag[r]; // stash kd - diag
        }
        #pragma unroll
        for (int o = 16; o; o >>= 1) bm = fmaxf(bm, __shfl_xor_sync(0xffffffffu, bm, o));
        if (lane == 0) sRed[w] = bm;
        __syncthreads();
        if (tid == 0) {
            float m2 = sRed[0];
            #pragma unroll
            for (int i = 1; i < 8; i++) m2 = fmaxf(m2, sRed[i]);
            unsigned u = __float_as_uint(m2);
            unsigned key = (u & 0x80000000u) ? ~u : (u | 0x80000000u);
            atomicMax(&g_kmax_bits, key);   // deterministic (max is order-independent)
        }
    }
}

// ---------------------------------------------------------------------------
// k' = ratio*(exp(kd - diag - stab) + eps), in place; plus column-sum partials.
// ---------------------------------------------------------------------------
__global__ void __launch_bounds__(256) k_ktrans()
{
    const int bh = blockIdx.y;
    const int r0 = blockIdx.x * 256;
    unsigned key = g_kmax_bits;
    unsigned u = (key & 0x80000000u) ? (key & 0x7FFFFFFFu) : ~key;
    const float stab = __uint_as_float(u);

    const int m1 = threadIdx.x;
    const bool has2 = m1 < (MM - 256);
    const int m2 = m1 + 256;
    float s1 = 0.f, s2 = 0.f;
    float* base = g_kd + ((size_t)bh * NN + r0) * MSTR;
    for (int r = 0; r < 256; r++) {
        float* p = base + (size_t)r * MSTR;
        float v1 = RATIO * (__expf(p[m1] - stab) + EPSV);
        p[m1] = v1; s1 += v1;
        if (has2) {
            float v2 = RATIO * (__expf(p[m2] - stab) + EPSV);
            p[m2] = v2; s2 += v2;
        }
    }
    float* part = g_kcum_part + ((size_t)blockIdx.x * BHc + bh) * MM;
    part[m1] = s1;
    if (has2) part[m2] = s2;
}

__global__ void k_kcum_reduce()
{
    const int bh = blockIdx.x;
    for (int m = threadIdx.x; m < MM; m += 256) {
        float s = 0.f;
        #pragma unroll
        for (int c = 0; c < KCHUNKS; c++)
            s += g_kcum_part[((size_t)c * BHc + bh) * MM + m];
        g_kcum[(size_t)bh * MM + m] = s;
    }
}

// ---------------------------------------------------------------------------
// context[m][e] = sum_n k'[n][m] * v[n][e], split-K over n into partials.
// ---------------------------------------------------------------------------
__global__ void __launch_bounds__(256) k_ctx(const float* __restrict__ V)
{
    __shared__ float sA[64 * 65];   // [kk][m_local]
    __shared__ float sB[64 * 65];   // [kk][e]
    const int tid = threadIdx.x;
    const int tx = tid & 15, ty = tid >> 4;
    const int m0 = blockIdx.x * 64;
    const int split = blockIdx.y;
    const int bh = blockIdx.z;
    const int n0 = split * (NN / SPLITK);
    const float* Kp = g_kd + (size_t)bh * NN * MSTR;
    const float* Vb = V + (size_t)bh * NN * EE;

    float acc[4][4];
    #pragma unroll
    for (int i = 0; i < 4; i++)
        #pragma unroll
        for (int j = 0; j < 4; j++) acc[i][j] = 0.f;

    const int c4 = (tid & 15) * 4;
    const int rr = tid >> 4;

    #pragma unroll 1
    for (int nc = 0; nc < NN / SPLITK; nc += 64) {
        __syncthreads();
        #pragma unroll
        for (int j = 0; j < 4; j++) {
            int kk = rr + 16 * j;
            size_t n = (size_t)(n0 + nc + kk);
            const float* srcA = Kp + n * MSTR + m0 + c4;
            float a0, a1, a2, a3;
            if (m0 + c4 + 3 < MM) {
                float4 v4 = *(const float4*)srcA;
                a0 = v4.x; a1 = v4.y; a2 = v4.z; a3 = v4.w;
            } else {
                a0 = (m0 + c4 + 0 < MM) ? srcA[0] : 0.f;
                a1 = (m0 + c4 + 1 < MM) ? srcA[1] : 0.f;
                a2 = (m0 + c4 + 2 < MM) ? srcA[2] : 0.f;
                a3 = (m0 + c4 + 3 < MM) ? srcA[3] : 0.f;
            }
            sA[kk * 65 + c4 + 0] = a0; sA[kk * 65 + c4 + 1] = a1;
            sA[kk * 65 + c4 + 2] = a2; sA[kk * 65 + c4 + 3] = a3;
            float4 bv = *(const float4*)(Vb + n * EE + c4);
            sB[kk * 65 + c4 + 0] = bv.x; sB[kk * 65 + c4 + 1] = bv.y;
            sB[kk * 65 + c4 + 2] = bv.z; sB[kk * 65 + c4 + 3] = bv.w;
        }
        __syncthreads();
        #pragma unroll 8
        for (int kk = 0; kk < 64; kk++) {
            float a[4], b[4];
            #pragma unroll
            for (int i = 0; i < 4; i++) a[i] = sA[kk * 65 + 4 * ty + i];
            #pragma unroll
            for (int j = 0; j < 4; j++) b[j] = sB[kk * 65 + 4 * tx + j];
            #pragma unroll
            for (int i = 0; i < 4; i++)
                #pragma unroll
                for (int j = 0; j < 4; j++)
                    acc[i][j] = fmaf(a[i], b[j], acc[i][j]);
        }
    }

    float* dst = g_ctx_part + ((size_t)split * BHc + bh) * MM * EE;
    #pragma unroll
    for (int i = 0; i < 4; i++) {
        int m = m0 + 4 * ty + i;
        if (m < MM) {
            float4 v4 = make_float4(acc[i][0], acc[i][1], acc[i][2], acc[i][3]);
            *(float4*)(dst + (size_t)m * EE + 4 * tx) = v4;
        }
    }
}

__global__ void k_ctx_reduce()
{
    size_t idx = (size_t)blockIdx.x * 256 + threadIdx.x;
    float s = 0.f;
    #pragma unroll
    for (int c = 0; c < SPLITK; c++)
        s += g_ctx_part[(size_t)c * (BHc * MM * EE) + idx];
    g_ctx[idx] = s;
}

// ---------------------------------------------------------------------------
// out[n][e] = (sum_m q'[n][m] ctx[m][e]) / (sum_m q'[n][m] kcum[m])
// ---------------------------------------------------------------------------
__global__ void __launch_bounds__(256) k_out(float* __restrict__ O)
{
    __shared__ float sA[64 * 65];   // [kk(m)][r]
    __shared__ float sB[64 * 65];   // [kk][e]
    __shared__ float sC[320];       // kcum, zero-padded
    __shared__ float sDen[64];
    const int tid = threadIdx.x;
    const int tx = tid & 15, ty = tid >> 4;
    const int bh = blockIdx.y;
    const int n0 = blockIdx.x * 64;
    const float* Qp = g_qp + ((size_t)bh * NN + n0) * MSTR;
    const float* Cx = g_ctx + (size_t)bh * MM * EE;

    for (int m = tid; m < 320; m += 256)
        sC[m] = (m < MM) ? g_kcum[(size_t)bh * MM + m] : 0.f;
    if (tid < 64) sDen[tid] = 0.f;

    float acc[4][4];
    #pragma unroll
    for (int i = 0; i < 4; i++)
        #pragma unroll
        for (int j = 0; j < 4; j++) acc[i][j] = 0.f;

    const int k4 = (tid & 15) * 4;
    const int rr = tid >> 4;

    #pragma unroll 1
    for (int t = 0; t < 5; t++) {
        const int m0 = t * 64;
        __syncthreads();
        #pragma unroll
        for (int j = 0; j < 4; j++) {
            int r = rr + 16 * j;
            const float* src = Qp + (size_t)r * MSTR + m0 + k4;
            float x0, x1, x2, x3;
            if (m0 + k4 + 3 < MM) {
                float4 v = *(const float4*)src;
                x0 = v.x; x1 = v.y; x2 = v.z; x3 = v.w;
            } else {
                x0 = (m0 + k4 + 0 < MM) ? src[0] : 0.f;
                x1 = (m0 + k4 + 1 < MM) ? src[1] : 0.f;
                x2 = (m0 + k4 + 2 < MM) ? src[2] : 0.f;
                x3 = (m0 + k4 + 3 < MM) ? src[3] : 0.f;
            }
            sA[(k4 + 0) * 65 + r] = x0; sA[(k4 + 1) * 65 + r] = x1;
            sA[(k4 + 2) * 65 + r] = x2; sA[(k4 + 3) * 65 + r] = x3;

            int kk = r;
            int m = m0 + kk;
            float4 bv = make_float4(0.f, 0.f, 0.f, 0.f);
            if (m < MM) bv = *(const float4*)(Cx + (size_t)m * EE + k4);
            sB[kk * 65 + k4 + 0] = bv.x; sB[kk * 65 + k4 + 1] = bv.y;
            sB[kk * 65 + k4 + 2] = bv.z; sB[kk * 65 + k4 + 3] = bv.w;
        }
        __syncthreads();
        if (tid < 64) {   // denominator accumulation (rows owned 1:1 by threads 0..63)
            float s = 0.f;
            #pragma unroll 8
            for (int kk = 0; kk < 64; kk++)
                s = fmaf(sA[kk * 65 + tid], sC[m0 + kk], s);
            sDen[tid] += s;
        }
        #pragma unroll 8
        for (int kk = 0; kk < 64; kk++) {
            float a[4], b[4];
            #pragma unroll
            for (int i = 0; i < 4; i++) a[i] = sA[kk * 65 + 4 * ty + i];
            #pragma unroll
            for (int j = 0; j < 4; j++) b[j] = sB[kk * 65 + 4 * tx + j];
            #pragma unroll
            for (int i = 0; i < 4; i++)
                #pragma unroll
                for (int j = 0; j < 4; j++)
                    acc[i][j] = fmaf(a[i], b[j], acc[i][j]);
        }
    }
    __syncthreads();

    float* Ob = O + ((size_t)bh * NN + n0) * EE;
    #pragma unroll
    for (int i = 0; i < 4; i++) {
        int r = 4 * ty + i;
        float dinv = 1.0f / sDen[r];
        float4 v4 = make_float4(acc[i][0] * dinv, acc[i][1] * dinv,
                                acc[i][2] * dinv, acc[i][3] * dinv);
        *(float4*)(Ob + (size_t)r * EE + 4 * tx) = v4;
    }
}

// ---------------------------------------------------------------------------
extern "C" void kernel_launch(void* const* d_in, const int* in_sizes, int n_in,
                              void* d_out, int out_size)
{
    const float* q = (const float*)d_in[0];
    const float* k = (const float*)d_in[1];
    const float* v = (const float*)d_in[2];
    const float* P = (const float*)d_in[3];
    float* out = (float*)d_out;

    const int smem_proj = (2 * 64 * 65 + 64 * 272 + 64 + 64 + 8) * (int)sizeof(float);
    cudaFuncSetAttribute(k_proj<true>,  cudaFuncAttributeMaxDynamicSharedMemorySize, smem_proj);
    cudaFuncSetAttribute(k_proj<false>, cudaFuncAttributeMaxDynamicSharedMemorySize, smem_proj);

    k_reset<<<1, 32>>>();
    k_proj<true><<<dim3(NN / 64, BHc), 256, smem_proj>>>(q, P);
    k_proj<false><<<dim3(NN / 64, BHc), 256, smem_proj>>>(k, P);
    k_ktrans<<<dim3(NN / 256, BHc), 256>>>();
    k_kcum_reduce<<<BHc, 256>>>();
    k_ctx<<<dim3((MM + 63) / 64, SPLITK, BHc), 256>>>(v);
    k_ctx_reduce<<<(BHc * MM * EE) / 256, 256>>>();
    k_out<<<dim3(NN / 64, BHc), 256>>>(out);
}

// round 4
// speedup vs baseline: 1.3258x; 1.3258x over previous
#include <cuda_runtime.h>
#include <cstdint>

// FastAttention (Performer / FAVOR+) — B=4 H=8 N=4096 D=64 M=266 E=64.
// Round 4: tcgen05 unavailable (harness PTX targets base compute_103).
// Projection GEMMs now use mma.sync tf32 (sm_80+ portable) with 3xTF32
// decomposition. ctx/out GEMMs identical to the round-2 passing kernel.

#define BHc 32
#define NN  4096
#define DD  64
#define MM  266
#define MSTR 272
#define EE  64

#define DN     0.3535533905932738f
#define RATIO  0.06131393394849658f
#define EPSV   1e-4f
#define NEGINF (-3.402823466e38f)

#define KCHUNKS 16
#define SPLITK  4

// ---- scratch ----
__device__ float    g_qp[BHc * NN * MSTR];
__device__ float    g_kd[BHc * NN * MSTR];
__device__ unsigned g_kmax_bits;
__device__ float    g_kcum_part[KCHUNKS * BHc * MM];
__device__ float    g_kcum[BHc * MM];
__device__ float    g_ctx_part[SPLITK * BHc * MM * EE];
__device__ float    g_ctx[BHc * MM * EE];

__global__ void k_reset() { if (threadIdx.x == 0) g_kmax_bits = 0u; }

// =====================  mma.sync helpers  ======================

__device__ __forceinline__ uint32_t f2tf32(float x) {
    uint32_t r; asm("cvt.rna.tf32.f32 %0, %1;" : "=r"(r) : "f"(x)); return r;
}
__device__ __forceinline__ void mma8(float* d, const uint32_t* a, const uint32_t* b) {
    asm volatile(
        "mma.sync.aligned.m16n8k8.row.col.f32.tf32.tf32.f32 "
        "{%0,%1,%2,%3}, {%4,%5,%6,%7}, {%8,%9}, {%0,%1,%2,%3};"
        : "+f"(d[0]), "+f"(d[1]), "+f"(d[2]), "+f"(d[3])
        : "r"(a[0]), "r"(a[1]), "r"(a[2]), "r"(a[3]), "r"(b[0]), "r"(b[1]));
}

// ===========================================================================
// dash GEMM via mma.sync tf32x3: one CTA = 64 n-rows x 272 m-cols x K=64.
// 8 warps = 4 row-groups(16) x 2 col-halves(136 = 17 n8-tiles).
// Q: fused per-row max + exp epilogue -> writes q' final.
// K: writes (dash - diag) + deterministic ordered-uint global atomicMax.
// ===========================================================================
#define SXS 68          // padded strides: 68 mod 32 == 4 -> conflict-free frags
#define SPS 68

template <bool IS_Q>
__global__ void __launch_bounds__(256, 2) k_dash_mma(const float* __restrict__ X,
                                                     const float* __restrict__ P)
{
    extern __shared__ float sh[];
    float* sX    = sh;                    // [64][68]
    float* sP    = sh + 64 * SXS;         // [272][68]
    float* sDiag = sP + 272 * SPS;        // [64]
    float* sMaxH = sDiag + 64;            // [2][64]
    float* sRed  = sMaxH + 128;           // [8]

    const int tid = threadIdx.x, lane = tid & 31, wid = tid >> 5;
    const int bh = blockIdx.y, n0 = blockIdx.x * 64;

    // ---- load X tile (scaled by DN) + per-row diag ----
    {
        const int row = tid >> 2, kq = (tid & 3) * 16;
        const float* src = X + ((size_t)bh * NN + n0 + row) * DD + kq;
        float ss = 0.f;
        #pragma unroll
        for (int j = 0; j < 4; j++) {
            float4 v = *(const float4*)(src + j * 4);
            float x0 = v.x * DN, x1 = v.y * DN, x2 = v.z * DN, x3 = v.w * DN;
            float* d = sX + row * SXS + kq + j * 4;
            d[0] = x0; d[1] = x1; d[2] = x2; d[3] = x3;
            ss = fmaf(x0, x0, ss); ss = fmaf(x1, x1, ss);
            ss = fmaf(x2, x2, ss); ss = fmaf(x3, x3, ss);
        }
        ss += __shfl_xor_sync(0xffffffffu, ss, 1);
        ss += __shfl_xor_sync(0xffffffffu, ss, 2);
        if ((tid & 3) == 0) sDiag[row] = 0.5f * ss;
    }

    // ---- load P (272 rows, zero-padded past 266) ----
    for (int t = tid; t < 272 * 4; t += 256) {
        const int row = t >> 2, kq = (t & 3) * 16;
        const bool valid = row < MM;
        const float* src = P + (size_t)row * DD + kq;
        float* d = sP + row * SPS + kq;
        #pragma unroll
        for (int j = 0; j < 4; j++) {
            float4 v = valid ? *(const float4*)(src + j * 4)
                             : make_float4(0.f, 0.f, 0.f, 0.f);
            d[j * 4 + 0] = v.x; d[j * 4 + 1] = v.y;
            d[j * 4 + 2] = v.z; d[j * 4 + 3] = v.w;
        }
    }
    __syncthreads();

    const int rowGroup = wid >> 1, half = wid & 1;
    const int rA = rowGroup * 16 + (lane >> 2);        // local row (c0/c1)
    const int colBase = half * 136;

    float acc[17][4];
    #pragma unroll
    for (int t = 0; t < 17; t++)
        #pragma unroll
        for (int j = 0; j < 4; j++) acc[t][j] = 0.f;

    #pragma unroll 1
    for (int k0 = 0; k0 < 64; k0 += 8) {
        const float* ax = sX + (size_t)rA * SXS + k0 + (lane & 3);
        float a0 = ax[0], a1 = ax[8 * SXS], a2 = ax[4], a3 = ax[8 * SXS + 4];
        uint32_t aH[4], aL[4];
        aH[0] = f2tf32(a0); aL[0] = f2tf32(a0 - __uint_as_float(aH[0]));
        aH[1] = f2tf32(a1); aL[1] = f2tf32(a1 - __uint_as_float(aH[1]));
        aH[2] = f2tf32(a2); aL[2] = f2tf32(a2 - __uint_as_float(aH[2]));
        aH[3] = f2tf32(a3); aL[3] = f2tf32(a3 - __uint_as_float(aH[3]));

        #pragma unroll
        for (int t = 0; t < 17; t++) {
            const float* bx = sP + (size_t)(colBase + t * 8 + (lane >> 2)) * SPS
                              + k0 + (lane & 3);
            float b0 = bx[0], b1 = bx[4];
            uint32_t bH[2], bL[2];
            bH[0] = f2tf32(b0); bL[0] = f2tf32(b0 - __uint_as_float(bH[0]));
            bH[1] = f2tf32(b1); bL[1] = f2tf32(b1 - __uint_as_float(bH[1]));
            mma8(acc[t], aH, bH);
            mma8(acc[t], aH, bL);
            mma8(acc[t], aL, bH);
        }
    }

    const float dgA = sDiag[rA], dgB = sDiag[rA + 8];

    if (IS_Q) {
        // per-row max (masked to m < MM)
        float mA = NEGINF, mB = NEGINF;
        #pragma unroll
        for (int t = 0; t < 17; t++) {
            int m0 = colBase + t * 8 + (lane & 3) * 2;
            if (m0 < MM)     { mA = fmaxf(mA, acc[t][0]); mB = fmaxf(mB, acc[t][2]); }
            if (m0 + 1 < MM) { mA = fmaxf(mA, acc[t][1]); mB = fmaxf(mB, acc[t][3]); }
        }
        mA = fmaxf(mA, __shfl_xor_sync(0xffffffffu, mA, 1));
        mA = fmaxf(mA, __shfl_xor_sync(0xffffffffu, mA, 2));
        mB = fmaxf(mB, __shfl_xor_sync(0xffffffffu, mB, 1));
        mB = fmaxf(mB, __shfl_xor_sync(0xffffffffu, mB, 2));
        if ((lane & 3) == 0) {
            sMaxH[half * 64 + rA]     = mA;
            sMaxH[half * 64 + rA + 8] = mB;
        }
        __syncthreads();
        const float mxA = fmaxf(sMaxH[rA],     sMaxH[64 + rA]);
        const float mxB = fmaxf(sMaxH[rA + 8], sMaxH[64 + rA + 8]);

        float* outb = g_qp + ((size_t)bh * NN + n0) * MSTR;
        #pragma unroll
        for (int t = 0; t < 17; t++) {
            int m0 = colBase + t * 8 + (lane & 3) * 2;
            float2 vA = make_float2(RATIO * (__expf(acc[t][0] - dgA - mxA) + EPSV),
                                    RATIO * (__expf(acc[t][1] - dgA - mxA) + EPSV));
            float2 vB = make_float2(RATIO * (__expf(acc[t][2] - dgB - mxB) + EPSV),
                                    RATIO * (__expf(acc[t][3] - dgB - mxB) + EPSV));
            *(float2*)(outb + (size_t)rA * MSTR + m0)       = vA;
            *(float2*)(outb + (size_t)(rA + 8) * MSTR + m0) = vB;
        }
    } else {
        float bm = NEGINF;
        float* outb = g_kd + ((size_t)bh * NN + n0) * MSTR;
        #pragma unroll
        for (int t = 0; t < 17; t++) {
            int m0 = colBase + t * 8 + (lane & 3) * 2;
            if (m0 < MM)     { bm = fmaxf(bm, fmaxf(acc[t][0], acc[t][2])); }
            if (m0 + 1 < MM) { bm = fmaxf(bm, fmaxf(acc[t][1], acc[t][3])); }
            float2 vA = make_float2(acc[t][0] - dgA, acc[t][1] - dgA);
            float2 vB = make_float2(acc[t][2] - dgB, acc[t][3] - dgB);
            *(float2*)(outb + (size_t)rA * MSTR + m0)       = vA;
            *(float2*)(outb + (size_t)(rA + 8) * MSTR + m0) = vB;
        }
        #pragma unroll
        for (int o = 16; o; o >>= 1) bm = fmaxf(bm, __shfl_xor_sync(0xffffffffu, bm, o));
        if (lane == 0) sRed[wid] = bm;
        __syncthreads();
        if (tid == 0) {
            float m2 = sRed[0];
            #pragma unroll
            for (int i = 1; i < 8; i++) m2 = fmaxf(m2, sRed[i]);
            unsigned u = __float_as_uint(m2);
            unsigned key = (u & 0x80000000u) ? ~u : (u | 0x80000000u);
            atomicMax(&g_kmax_bits, key);   // deterministic (max is order-independent)
        }
    }
}

#define SMEM_DASH ((64 * SXS + 272 * SPS + 64 + 128 + 8) * (int)sizeof(float))

// ---------------------------------------------------------------------------
// k' = ratio*(exp(kd - stab) + eps), in place; plus column-sum partials.
// ---------------------------------------------------------------------------
__global__ void __launch_bounds__(256) k_ktrans()
{
    const int bh = blockIdx.y;
    const int r0 = blockIdx.x * 256;
    unsigned key = g_kmax_bits;
    unsigned u = (key & 0x80000000u) ? (key & 0x7FFFFFFFu) : ~key;
    const float stab = __uint_as_float(u);

    const int m1 = threadIdx.x;
    const bool has2 = m1 < (MM - 256);
    const int m2 = m1 + 256;
    float s1 = 0.f, s2 = 0.f;
    float* base = g_kd + ((size_t)bh * NN + r0) * MSTR;
    for (int r = 0; r < 256; r++) {
        float* p = base + (size_t)r * MSTR;
        float v1 = RATIO * (__expf(p[m1] - stab) + EPSV);
        p[m1] = v1; s1 += v1;
        if (has2) {
            float v2 = RATIO * (__expf(p[m2] - stab) + EPSV);
            p[m2] = v2; s2 += v2;
        }
    }
    float* part = g_kcum_part + ((size_t)blockIdx.x * BHc + bh) * MM;
    part[m1] = s1;
    if (has2) part[m2] = s2;
}

__global__ void k_kcum_reduce()
{
    const int bh = blockIdx.x;
    for (int m = threadIdx.x; m < MM; m += 256) {
        float s = 0.f;
        #pragma unroll
        for (int c = 0; c < KCHUNKS; c++)
            s += g_kcum_part[((size_t)c * BHc + bh) * MM + m];
        g_kcum[(size_t)bh * MM + m] = s;
    }
}

// ---------------------------------------------------------------------------
// context[m][e] = sum_n k'[n][m] * v[n][e], split-K over n into partials.
// ---------------------------------------------------------------------------
__global__ void __launch_bounds__(256) k_ctx(const float* __restrict__ V)
{
    __shared__ float sA[64 * 65];
    __shared__ float sB[64 * 65];
    const int tid = threadIdx.x;
    const int tx = tid & 15, ty = tid >> 4;
    const int m0 = blockIdx.x * 64;
    const int split = blockIdx.y;
    const int bh = blockIdx.z;
    const int n0 = split * (NN / SPLITK);
    const float* Kp = g_kd + (size_t)bh * NN * MSTR;
    const float* Vb = V + (size_t)bh * NN * EE;

    float acc[4][4];
    #pragma unroll
    for (int i = 0; i < 4; i++)
        #pragma unroll
        for (int j = 0; j < 4; j++) acc[i][j] = 0.f;

    const int c4 = (tid & 15) * 4;
    const int rr = tid >> 4;

    #pragma unroll 1
    for (int nc = 0; nc < NN / SPLITK; nc += 64) {
        __syncthreads();
        #pragma unroll
        for (int j = 0; j < 4; j++) {
            int kk = rr + 16 * j;
            size_t n = (size_t)(n0 + nc + kk);
            const float* srcA = Kp + n * MSTR + m0 + c4;
            float a0, a1, a2, a3;
            if (m0 + c4 + 3 < MM) {
                float4 v4 = *(const float4*)srcA;
                a0 = v4.x; a1 = v4.y; a2 = v4.z; a3 = v4.w;
            } else {
                a0 = (m0 + c4 + 0 < MM) ? srcA[0] : 0.f;
                a1 = (m0 + c4 + 1 < MM) ? srcA[1] : 0.f;
                a2 = (m0 + c4 + 2 < MM) ? srcA[2] : 0.f;
                a3 = (m0 + c4 + 3 < MM) ? srcA[3] : 0.f;
            }
            sA[kk * 65 + c4 + 0] = a0; sA[kk * 65 + c4 + 1] = a1;
            sA[kk * 65 + c4 + 2] = a2; sA[kk * 65 + c4 + 3] = a3;
            float4 bv = *(const float4*)(Vb + n * EE + c4);
            sB[kk * 65 + c4 + 0] = bv.x; sB[kk * 65 + c4 + 1] = bv.y;
            sB[kk * 65 + c4 + 2] = bv.z; sB[kk * 65 + c4 + 3] = bv.w;
        }
        __syncthreads();
        #pragma unroll 8
        for (int kk = 0; kk < 64; kk++) {
            float a[4], b[4];
            #pragma unroll
            for (int i = 0; i < 4; i++) a[i] = sA[kk * 65 + 4 * ty + i];
            #pragma unroll
            for (int j = 0; j < 4; j++) b[j] = sB[kk * 65 + 4 * tx + j];
            #pragma unroll
            for (int i = 0; i < 4; i++)
                #pragma unroll
                for (int j = 0; j < 4; j++)
                    acc[i][j] = fmaf(a[i], b[j], acc[i][j]);
        }
    }

    float* dst = g_ctx_part + ((size_t)split * BHc + bh) * MM * EE;
    #pragma unroll
    for (int i = 0; i < 4; i++) {
        int m = m0 + 4 * ty + i;
        if (m < MM) {
            float4 v4 = make_float4(acc[i][0], acc[i][1], acc[i][2], acc[i][3]);
            *(float4*)(dst + (size_t)m * EE + 4 * tx) = v4;
        }
    }
}

__global__ void k_ctx_reduce()
{
    size_t idx = (size_t)blockIdx.x * 256 + threadIdx.x;
    float s = 0.f;
    #pragma unroll
    for (int c = 0; c < SPLITK; c++)
        s += g_ctx_part[(size_t)c * (BHc * MM * EE) + idx];
    g_ctx[idx] = s;
}

// ---------------------------------------------------------------------------
// out[n][e] = (sum_m q'[n][m] ctx[m][e]) / (sum_m q'[n][m] kcum[m])
// ---------------------------------------------------------------------------
__global__ void __launch_bounds__(256) k_out(float* __restrict__ O)
{
    __shared__ float sA[64 * 65];
    __shared__ float sB[64 * 65];
    __shared__ float sC[320];
    __shared__ float sDen[64];
    const int tid = threadIdx.x;
    const int tx = tid & 15, ty = tid >> 4;
    const int bh = blockIdx.y;
    const int n0 = blockIdx.x * 64;
    const float* Qp = g_qp + ((size_t)bh * NN + n0) * MSTR;
    const float* Cx = g_ctx + (size_t)bh * MM * EE;

    for (int m = tid; m < 320; m += 256)
        sC[m] = (m < MM) ? g_kcum[(size_t)bh * MM + m] : 0.f;
    if (tid < 64) sDen[tid] = 0.f;

    float acc[4][4];
    #pragma unroll
    for (int i = 0; i < 4; i++)
        #pragma unroll
        for (int j = 0; j < 4; j++) acc[i][j] = 0.f;

    const int k4 = (tid & 15) * 4;
    const int rr = tid >> 4;

    #pragma unroll 1
    for (int t = 0; t < 5; t++) {
        const int m0 = t * 64;
        __syncthreads();
        #pragma unroll
        for (int j = 0; j < 4; j++) {
            int r = rr + 16 * j;
            const float* src = Qp + (size_t)r * MSTR + m0 + k4;
            float x0, x1, x2, x3;
            if (m0 + k4 + 3 < MM) {
                float4 v = *(const float4*)src;
                x0 = v.x; x1 = v.y; x2 = v.z; x3 = v.w;
            } else {
                x0 = (m0 + k4 + 0 < MM) ? src[0] : 0.f;
                x1 = (m0 + k4 + 1 < MM) ? src[1] : 0.f;
                x2 = (m0 + k4 + 2 < MM) ? src[2] : 0.f;
                x3 = (m0 + k4 + 3 < MM) ? src[3] : 0.f;
            }
            sA[(k4 + 0) * 65 + r] = x0; sA[(k4 + 1) * 65 + r] = x1;
            sA[(k4 + 2) * 65 + r] = x2; sA[(k4 + 3) * 65 + r] = x3;

            int kk = r;
            int m = m0 + kk;
            float4 bv = make_float4(0.f, 0.f, 0.f, 0.f);
            if (m < MM) bv = *(const float4*)(Cx + (size_t)m * EE + k4);
            sB[kk * 65 + k4 + 0] = bv.x; sB[kk * 65 + k4 + 1] = bv.y;
            sB[kk * 65 + k4 + 2] = bv.z; sB[kk * 65 + k4 + 3] = bv.w;
        }
        __syncthreads();
        if (tid < 64) {
            float s = 0.f;
            #pragma unroll 8
            for (int kk = 0; kk < 64; kk++)
                s = fmaf(sA[kk * 65 + tid], sC[m0 + kk], s);
            sDen[tid] += s;
        }
        #pragma unroll 8
        for (int kk = 0; kk < 64; kk++) {
            float a[4], b[4];
            #pragma unroll
            for (int i = 0; i < 4; i++) a[i] = sA[kk * 65 + 4 * ty + i];
            #pragma unroll
            for (int j = 0; j < 4; j++) b[j] = sB[kk * 65 + 4 * tx + j];
            #pragma unroll
            for (int i = 0; i < 4; i++)
                #pragma unroll
                for (int j = 0; j < 4; j++)
                    acc[i][j] = fmaf(a[i], b[j], acc[i][j]);
        }
    }
    __syncthreads();

    float* Ob = O + ((size_t)bh * NN + n0) * EE;
    #pragma unroll
    for (int i = 0; i < 4; i++) {
        int r = 4 * ty + i;
        float dinv = 1.0f / sDen[r];
        float4 v4 = make_float4(acc[i][0] * dinv, acc[i][1] * dinv,
                                acc[i][2] * dinv, acc[i][3] * dinv);
        *(float4*)(Ob + (size_t)r * EE + 4 * tx) = v4;
    }
}

// ---------------------------------------------------------------------------
extern "C" void kernel_launch(void* const* d_in, const int* in_sizes, int n_in,
                              void* d_out, int out_size)
{
    const float* q = (const float*)d_in[0];
    const float* k = (const float*)d_in[1];
    const float* v = (const float*)d_in[2];
    const float* P = (const float*)d_in[3];
    float* out = (float*)d_out;

    cudaFuncSetAttribute(k_dash_mma<true>,  cudaFuncAttributeMaxDynamicSharedMemorySize, SMEM_DASH);
    cudaFuncSetAttribute(k_dash_mma<false>, cudaFuncAttributeMaxDynamicSharedMemorySize, SMEM_DASH);

    k_reset<<<1, 32>>>();
    k_dash_mma<true><<<dim3(NN / 64, BHc), 256, SMEM_DASH>>>(q, P);
    k_dash_mma<false><<<dim3(NN / 64, BHc), 256, SMEM_DASH>>>(k, P);
    k_ktrans<<<dim3(NN / 256, BHc), 256>>>();
    k_kcum_reduce<<<BHc, 256>>>();
    k_ctx<<<dim3((MM + 63) / 64, SPLITK, BHc), 256>>>(v);
    k_ctx_reduce<<<(BHc * MM * EE) / 256, 256>>>();
    k_out<<<dim3(NN / 64, BHc), 256>>>(out);
}

// round 6
// speedup vs baseline: 1.4875x; 1.1219x over previous
#include <cuda_runtime.h>
#include <cstdint>

// FastAttention (Performer / FAVOR+) — B=4 H=8 N=4096 D=64 M=266 E=64.
// Round 6: fix smem float4 misalignment in k_out_mma (stride 65 -> 68).
// All three GEMM stages on mma.sync tf32x3; exp fused into ctx A-load;
// kcum as ones-column; ctx transposed; denominator fused as out col 64.

#define BHc 32
#define NN  4096
#define DD  64
#define MM  266
#define MSTR 272
#define EE  64
#define ECT 80            // ctx cols: 64 v + ones(kcum) at 64 + 15 zero pad

#define DN     0.3535533905932738f
#define RATIO  0.06131393394849658f
#define EPSV   1e-4f
#define NEGINF (-3.402823466e38f)

#define SPLITC 2

// ---- scratch ----
__device__ float    g_qp[BHc * NN * MSTR];       // q' (pads [266,272) stay 0)
__device__ float    g_kd[BHc * NN * MSTR];       // dash - diag (pads stay 0)
__device__ unsigned g_kmax_bits;
__device__ float    g_ctx_part[SPLITC * BHc * ECT * MSTR];
__device__ float    g_ctxT[BHc * ECT * MSTR];    // [bh][e][m]; row 64 = kcum

__global__ void k_reset() { if (threadIdx.x == 0) g_kmax_bits = 0u; }

// =====================  mma.sync helpers  ======================

__device__ __forceinline__ uint32_t f2tf32(float x) {
    uint32_t r; asm("cvt.rna.tf32.f32 %0, %1;" : "=r"(r) : "f"(x)); return r;
}
__device__ __forceinline__ void mma8(float* d, const uint32_t* a, const uint32_t* b) {
    asm volatile(
        "mma.sync.aligned.m16n8k8.row.col.f32.tf32.tf32.f32 "
        "{%0,%1,%2,%3}, {%4,%5,%6,%7}, {%8,%9}, {%0,%1,%2,%3};"
        : "+f"(d[0]), "+f"(d[1]), "+f"(d[2]), "+f"(d[3])
        : "r"(a[0]), "r"(a[1]), "r"(a[2]), "r"(a[3]), "r"(b[0]), "r"(b[1]));
}
__device__ __forceinline__ void splitA(const float* ax, int strd, uint32_t* aH, uint32_t* aL) {
    float a0 = ax[0], a1 = ax[8 * strd], a2 = ax[4], a3 = ax[8 * strd + 4];
    aH[0] = f2tf32(a0); aL[0] = f2tf32(a0 - __uint_as_float(aH[0]));
    aH[1] = f2tf32(a1); aL[1] = f2tf32(a1 - __uint_as_float(aH[1]));
    aH[2] = f2tf32(a2); aL[2] = f2tf32(a2 - __uint_as_float(aH[2]));
    aH[3] = f2tf32(a3); aL[3] = f2tf32(a3 - __uint_as_float(aH[3]));
}
__device__ __forceinline__ void splitB(const float* bx, uint32_t* bH, uint32_t* bL) {
    float b0 = bx[0], b1 = bx[4];
    bH[0] = f2tf32(b0); bL[0] = f2tf32(b0 - __uint_as_float(bH[0]));
    bH[1] = f2tf32(b1); bL[1] = f2tf32(b1 - __uint_as_float(bH[1]));
}

// ===========================================================================
// dash GEMM: CTA = 64 n-rows x 272 m x K=64. 8 warps = 4 rowgroups x 2 halves.
// ===========================================================================
#define SXS 68
#define SPS 68

template <bool IS_Q>
__global__ void __launch_bounds__(256, 2) k_dash_mma(const float* __restrict__ X,
                                                     const float* __restrict__ P)
{
    extern __shared__ float sh[];
    float* sX    = sh;                    // [64][68]
    float* sP    = sh + 64 * SXS;         // [272][68]
    float* sDiag = sP + 272 * SPS;        // [64]
    float* sMaxH = sDiag + 64;            // [2][64]
    float* sRed  = sMaxH + 128;           // [8]

    const int tid = threadIdx.x, lane = tid & 31, wid = tid >> 5;
    const int bh = blockIdx.y, n0 = blockIdx.x * 64;

    {   // X tile (scaled) + per-row diag
        const int row = tid >> 2, kq = (tid & 3) * 16;
        const float* src = X + ((size_t)bh * NN + n0 + row) * DD + kq;
        float ss = 0.f;
        #pragma unroll
        for (int j = 0; j < 4; j++) {
            float4 v = *(const float4*)(src + j * 4);
            float x0 = v.x * DN, x1 = v.y * DN, x2 = v.z * DN, x3 = v.w * DN;
            float* d = sX + row * SXS + kq + j * 4;
            d[0] = x0; d[1] = x1; d[2] = x2; d[3] = x3;
            ss = fmaf(x0, x0, ss); ss = fmaf(x1, x1, ss);
            ss = fmaf(x2, x2, ss); ss = fmaf(x3, x3, ss);
        }
        ss += __shfl_xor_sync(0xffffffffu, ss, 1);
        ss += __shfl_xor_sync(0xffffffffu, ss, 2);
        if ((tid & 3) == 0) sDiag[row] = 0.5f * ss;
    }
    for (int t = tid; t < 272 * 4; t += 256) {   // P (zero-padded past 266)
        const int row = t >> 2, kq = (t & 3) * 16;
        const bool valid = row < MM;
        const float* src = P + (size_t)row * DD + kq;
        float* d = sP + row * SPS + kq;
        #pragma unroll
        for (int j = 0; j < 4; j++) {
            float4 v = valid ? *(const float4*)(src + j * 4)
                             : make_float4(0.f, 0.f, 0.f, 0.f);
            d[j * 4 + 0] = v.x; d[j * 4 + 1] = v.y;
            d[j * 4 + 2] = v.z; d[j * 4 + 3] = v.w;
        }
    }
    __syncthreads();

    const int rowGroup = wid >> 1, half = wid & 1;
    const int rA = rowGroup * 16 + (lane >> 2);
    const int colBase = half * 136;

    float acc[17][4];
    #pragma unroll
    for (int t = 0; t < 17; t++)
        #pragma unroll
        for (int j = 0; j < 4; j++) acc[t][j] = 0.f;

    #pragma unroll 1
    for (int k0 = 0; k0 < 64; k0 += 8) {
        uint32_t aH[4], aL[4];
        splitA(sX + (size_t)rA * SXS + k0 + (lane & 3), SXS, aH, aL);
        #pragma unroll
        for (int t = 0; t < 17; t++) {
            uint32_t bH[2], bL[2];
            splitB(sP + (size_t)(colBase + t * 8 + (lane >> 2)) * SPS + k0 + (lane & 3), bH, bL);
            mma8(acc[t], aH, bH);
            mma8(acc[t], aH, bL);
            mma8(acc[t], aL, bH);
        }
    }

    const float dgA = sDiag[rA], dgB = sDiag[rA + 8];

    if (IS_Q) {
        float mA = NEGINF, mB = NEGINF;
        #pragma unroll
        for (int t = 0; t < 17; t++) {
            int m0 = colBase + t * 8 + (lane & 3) * 2;
            if (m0 < MM) {
                mA = fmaxf(mA, fmaxf(acc[t][0], acc[t][1]));
                mB = fmaxf(mB, fmaxf(acc[t][2], acc[t][3]));
            }
        }
        mA = fmaxf(mA, __shfl_xor_sync(0xffffffffu, mA, 1));
        mA = fmaxf(mA, __shfl_xor_sync(0xffffffffu, mA, 2));
        mB = fmaxf(mB, __shfl_xor_sync(0xffffffffu, mB, 1));
        mB = fmaxf(mB, __shfl_xor_sync(0xffffffffu, mB, 2));
        if ((lane & 3) == 0) {
            sMaxH[half * 64 + rA]     = mA;
            sMaxH[half * 64 + rA + 8] = mB;
        }
        __syncthreads();
        const float mxA = fmaxf(sMaxH[rA],     sMaxH[64 + rA]);
        const float mxB = fmaxf(sMaxH[rA + 8], sMaxH[64 + rA + 8]);

        float* outb = g_qp + ((size_t)bh * NN + n0) * MSTR;
        #pragma unroll
        for (int t = 0; t < 17; t++) {
            int m0 = colBase + t * 8 + (lane & 3) * 2;
            if (m0 < MM) {   // MM even, m0 even -> pair never straddles
                float2 vA = make_float2(RATIO * (__expf(acc[t][0] - dgA - mxA) + EPSV),
                                        RATIO * (__expf(acc[t][1] - dgA - mxA) + EPSV));
                float2 vB = make_float2(RATIO * (__expf(acc[t][2] - dgB - mxB) + EPSV),
                                        RATIO * (__expf(acc[t][3] - dgB - mxB) + EPSV));
                *(float2*)(outb + (size_t)rA * MSTR + m0)       = vA;
                *(float2*)(outb + (size_t)(rA + 8) * MSTR + m0) = vB;
            }
        }
    } else {
        float bm = NEGINF;
        float* outb = g_kd + ((size_t)bh * NN + n0) * MSTR;
        #pragma unroll
        for (int t = 0; t < 17; t++) {
            int m0 = colBase + t * 8 + (lane & 3) * 2;
            if (m0 < MM) {
                bm = fmaxf(bm, fmaxf(fmaxf(acc[t][0], acc[t][1]),
                                     fmaxf(acc[t][2], acc[t][3])));
                float2 vA = make_float2(acc[t][0] - dgA, acc[t][1] - dgA);
                float2 vB = make_float2(acc[t][2] - dgB, acc[t][3] - dgB);
                *(float2*)(outb + (size_t)rA * MSTR + m0)       = vA;
                *(float2*)(outb + (size_t)(rA + 8) * MSTR + m0) = vB;
            }
        }
        #pragma unroll
        for (int o = 16; o; o >>= 1) bm = fmaxf(bm, __shfl_xor_sync(0xffffffffu, bm, o));
        if (lane == 0) sRed[wid] = bm;
        __syncthreads();
        if (tid == 0) {
            float m2 = sRed[0];
            #pragma unroll
            for (int i = 1; i < 8; i++) m2 = fmaxf(m2, sRed[i]);
            unsigned u = __float_as_uint(m2);
            unsigned key = (u & 0x80000000u) ? ~u : (u | 0x80000000u);
            atomicMax(&g_kmax_bits, key);   // deterministic
        }
    }
}
#define SMEM_DASH ((64 * SXS + 272 * SPS + 64 + 128 + 8) * (int)sizeof(float))

// ===========================================================================
// ctx GEMM: ctxT[e][m] = sum_n k'[n][m] v[n][e], exp fused into A-load,
// ones-column at e=64 -> kcum. CTA = 64 m-rows x 80 e-cols, split-K over n.
// Scalar smem stores only -> stride 65 is safe here.
// ===========================================================================
#define SAS 65
#define SBS 65

__global__ void __launch_bounds__(256, 2) k_ctx_mma(const float* __restrict__ V)
{
    __shared__ float sA[64 * SAS];   // [m-local][n-local], transformed k'
    __shared__ float sB[ECT * SBS];  // [e][n-local]; row 64 = ones, 65..79 = 0

    const int tid = threadIdx.x, lane = tid & 31, wid = tid >> 5;
    const int m0 = blockIdx.x * 64;
    const int split = blockIdx.y, bh = blockIdx.z;
    const int n0 = split * (NN / SPLITC);

    unsigned key = g_kmax_bits;
    unsigned ub = (key & 0x80000000u) ? (key & 0x7FFFFFFFu) : ~key;
    const float stab = __uint_as_float(ub);

    const float* Kd = g_kd + (size_t)bh * NN * MSTR;
    const float* Vb = V + (size_t)bh * NN * EE;

    // static sB rows: ones at 64, zeros 65..79
    for (int idx = tid; idx < 16 * SBS; idx += 256)
        sB[64 * SBS + idx] = (idx < SBS) ? 1.f : 0.f;

    const int rowGroup = wid >> 1, half = wid & 1;
    const int rA = rowGroup * 16 + (lane >> 2);
    const int colBase = half * 40;

    float acc[5][4];
    #pragma unroll
    for (int t = 0; t < 5; t++)
        #pragma unroll
        for (int j = 0; j < 4; j++) acc[t][j] = 0.f;

    const int r = tid >> 4;            // n-local base 0..15
    const int c4 = (tid & 15) * 4;     // local col group
    const int mg = m0 + c4;

    #pragma unroll 1
    for (int nc = 0; nc < NN / SPLITC; nc += 64) {
        __syncthreads();
        // A: k' chunk, transposed, exp transform fused
        #pragma unroll
        for (int j = 0; j < 4; j++) {
            int nl = r + 16 * j;
            float4 x = make_float4(0.f, 0.f, 0.f, 0.f);
            if (mg + 3 < MSTR)
                x = *(const float4*)(Kd + (size_t)(n0 + nc + nl) * MSTR + mg);
            float v0 = (mg + 0 < MM) ? RATIO * (__expf(x.x - stab) + EPSV) : 0.f;
            float v1 = (mg + 1 < MM) ? RATIO * (__expf(x.y - stab) + EPSV) : 0.f;
            float v2 = (mg + 2 < MM) ? RATIO * (__expf(x.z - stab) + EPSV) : 0.f;
            float v3 = (mg + 3 < MM) ? RATIO * (__expf(x.w - stab) + EPSV) : 0.f;
            sA[(c4 + 0) * SAS + nl] = v0;
            sA[(c4 + 1) * SAS + nl] = v1;
            sA[(c4 + 2) * SAS + nl] = v2;
            sA[(c4 + 3) * SAS + nl] = v3;
        }
        // B: v chunk, transposed
        #pragma unroll
        for (int j = 0; j < 4; j++) {
            int nl = r + 16 * j;
            float4 x = *(const float4*)(Vb + (size_t)(n0 + nc + nl) * EE + c4);
            sB[(c4 + 0) * SBS + nl] = x.x;
            sB[(c4 + 1) * SBS + nl] = x.y;
            sB[(c4 + 2) * SBS + nl] = x.z;
            sB[(c4 + 3) * SBS + nl] = x.w;
        }
        __syncthreads();

        #pragma unroll
        for (int k0 = 0; k0 < 64; k0 += 8) {
            uint32_t aH[4], aL[4];
            splitA(sA + (size_t)rA * SAS + k0 + (lane & 3), SAS, aH, aL);
            #pragma unroll
            for (int t = 0; t < 5; t++) {
                uint32_t bH[2], bL[2];
                splitB(sB + (size_t)(colBase + t * 8 + (lane >> 2)) * SBS + k0 + (lane & 3), bH, bL);
                mma8(acc[t], aH, bH);
                mma8(acc[t], aH, bL);
                mma8(acc[t], aL, bH);
            }
        }
    }

    float* dst = g_ctx_part + ((size_t)(split * BHc + bh)) * (ECT * MSTR);
    const int mA_ = m0 + rA, mB_ = m0 + rA + 8;
    #pragma unroll
    for (int t = 0; t < 5; t++) {
        int e0 = colBase + t * 8 + (lane & 3) * 2;
        if (mA_ < MSTR) {
            dst[(size_t)e0 * MSTR + mA_]       = acc[t][0];
            dst[(size_t)(e0 + 1) * MSTR + mA_] = acc[t][1];
        }
        if (mB_ < MSTR) {
            dst[(size_t)e0 * MSTR + mB_]       = acc[t][2];
            dst[(size_t)(e0 + 1) * MSTR + mB_] = acc[t][3];
        }
    }
}

__global__ void k_ctxT_reduce()
{
    size_t idx = (size_t)blockIdx.x * 256 + threadIdx.x;
    float s = 0.f;
    #pragma unroll
    for (int c = 0; c < SPLITC; c++)
        s += g_ctx_part[(size_t)c * (BHc * ECT * MSTR) + idx];
    g_ctxT[idx] = s;
}

// ===========================================================================
// out GEMM: out[n][e] = (q' @ ctxT^T)[n][e] / (q' @ kcum)[n], den = col 64.
// CTA = 64 n-rows x 80 cols, K = 272 (pads zero both sides).
// Strides 68 (16B-aligned rows) because A/B are loaded with float4.
// ===========================================================================
#define SOS 68

__global__ void __launch_bounds__(256, 2) k_out_mma(float* __restrict__ O)
{
    __shared__ float sA[64 * SOS];   // [n-local][k]
    __shared__ float sB[ECT * SOS];  // [e'][k]
    __shared__ float sDen[64];

    const int tid = threadIdx.x, lane = tid & 31, wid = tid >> 5;
    const int n0 = blockIdx.x * 64, bh = blockIdx.y;

    const float* Qp = g_qp + ((size_t)bh * NN + n0) * MSTR;
    const float* Ct = g_ctxT + (size_t)bh * ECT * MSTR;

    const int rowGroup = wid >> 1, half = wid & 1;
    const int rA = rowGroup * 16 + (lane >> 2);
    const int colBase = half * 40;

    float acc[5][4];
    #pragma unroll
    for (int t = 0; t < 5; t++)
        #pragma unroll
        for (int j = 0; j < 4; j++) acc[t][j] = 0.f;

    #pragma unroll 1
    for (int ch = 0; ch < 5; ch++) {
        const int k0g = ch * 64;
        const int kw = (ch == 4) ? 16 : 64;
        __syncthreads();
        {   // A: q' rows, direct
            const int row = tid >> 2, kq = (tid & 3) * 16;
            #pragma unroll
            for (int j = 0; j < 4; j++) {
                int k = kq + 4 * j;
                if (k < kw)
                    *(float4*)(sA + row * SOS + k) =
                        *(const float4*)(Qp + (size_t)row * MSTR + k0g + k);
            }
        }
        // B: ctxT rows, direct
        for (int idx = tid; idx < ECT * 16; idx += 256) {
            int e = idx >> 4, k4 = (idx & 15) * 4;
            if (k4 < kw)
                *(float4*)(sB + e * SOS + k4) =
                    *(const float4*)(Ct + (size_t)e * MSTR + k0g + k4);
        }
        __syncthreads();

        for (int k0 = 0; k0 < kw; k0 += 8) {
            uint32_t aH[4], aL[4];
            splitA(sA + (size_t)rA * SOS + k0 + (lane & 3), SOS, aH, aL);
            #pragma unroll
            for (int t = 0; t < 5; t++) {
                uint32_t bH[2], bL[2];
                splitB(sB + (size_t)(colBase + t * 8 + (lane >> 2)) * SOS + k0 + (lane & 3), bH, bL);
                mma8(acc[t], aH, bH);
                mma8(acc[t], aH, bL);
                mma8(acc[t], aL, bH);
            }
        }
    }

    // den: col 64 lives in half1, tile 3, (lane&3)==0
    if (half == 1 && (lane & 3) == 0) {
        sDen[rA]     = acc[3][0];
        sDen[rA + 8] = acc[3][2];
    }
    __syncthreads();
    const float dinvA = 1.f / sDen[rA];
    const float dinvB = 1.f / sDen[rA + 8];

    float* Ob = O + ((size_t)bh * NN + n0) * EE;
    #pragma unroll
    for (int t = 0; t < 5; t++) {
        int e0 = colBase + t * 8 + (lane & 3) * 2;
        if (e0 < EE) {
            *(float2*)(Ob + (size_t)rA * EE + e0) =
                make_float2(acc[t][0] * dinvA, acc[t][1] * dinvA);
            *(float2*)(Ob + (size_t)(rA + 8) * EE + e0) =
                make_float2(acc[t][2] * dinvB, acc[t][3] * dinvB);
        }
    }
}

// ---------------------------------------------------------------------------
extern "C" void kernel_launch(void* const* d_in, const int* in_sizes, int n_in,
                              void* d_out, int out_size)
{
    const float* q = (const float*)d_in[0];
    const float* k = (const float*)d_in[1];
    const float* v = (const float*)d_in[2];
    const float* P = (const float*)d_in[3];
    float* out = (float*)d_out;

    cudaFuncSetAttribute(k_dash_mma<true>,  cudaFuncAttributeMaxDynamicSharedMemorySize, SMEM_DASH);
    cudaFuncSetAttribute(k_dash_mma<false>, cudaFuncAttributeMaxDynamicSharedMemorySize, SMEM_DASH);

    k_reset<<<1, 32>>>();
    k_dash_mma<true><<<dim3(NN / 64, BHc), 256, SMEM_DASH>>>(q, P);
    k_dash_mma<false><<<dim3(NN / 64, BHc), 256, SMEM_DASH>>>(k, P);
    k_ctx_mma<<<dim3((MSTR + 63) / 64, SPLITC, BHc), 256>>>(v);
    k_ctxT_reduce<<<(BHc * ECT * MSTR) / 256, 256>>>();
    k_out_mma<<<dim3(NN / 64, BHc), 256>>>(out);
}